// round 5
// baseline (speedup 1.0000x reference)
#include <cuda_runtime.h>

// LightGCN: out = sum_i a_i * A^i X W + b  ==  sum_i a_i * A^i (X W) + b
// Propagate in 2-dim projected space. R5: 8 edges/thread with front-batched
// gathers to double gather MLP (scatter was latency-bound at issue=5.9%).

#define N_NODES 100000
#define N_EDGES 1600000
#define DIM     128
#define NLAYERS 3
#define EPT     8   // edges per thread

// buf[i] holds A^i (XW), 2 floats per node.
__device__ __align__(16) float g_buf0[2 * N_NODES];
__device__ __align__(16) float g_buf1[2 * N_NODES];
__device__ __align__(16) float g_buf2[2 * N_NODES];
__device__ __align__(16) float g_buf3[2 * N_NODES];

__device__ __forceinline__ float* buf_of(int i) {
    return i == 0 ? g_buf0 : i == 1 ? g_buf1 : i == 2 ? g_buf2 : g_buf3;
}

// one 8-byte vector RED instead of two scalar float atomics
__device__ __forceinline__ void red_add_v2(float* p, float a, float b) {
    asm volatile("red.global.add.v2.f32 [%0], {%1, %2};"
                 :: "l"(p), "f"(a), "f"(b) : "memory");
}

// ---------------------------------------------------------------------------
// buf0 = (embedding[node_idx]) @ W ; also zero buf1..buf3.
__global__ void k_init(const int* __restrict__ node_idx,
                       const float* __restrict__ emb,
                       const float* __restrict__ W) {
    int gtid = blockIdx.x * blockDim.x + threadIdx.x;
    int warp = gtid >> 5;
    int lane = threadIdx.x & 31;
    if (warp >= N_NODES) return;

    if (gtid < 2 * N_NODES) {
        g_buf1[gtid] = 0.f;
        g_buf2[gtid] = 0.f;
        g_buf3[gtid] = 0.f;
    }

    int src = node_idx[warp];
    float4 v = reinterpret_cast<const float4*>(emb + (long long)src * DIM)[lane];
    const float4* w4 = reinterpret_cast<const float4*>(W + lane * 8);
    float4 w01 = w4[0];   // k0c0 k0c1 k1c0 k1c1
    float4 w23 = w4[1];   // k2c0 k2c1 k3c0 k3c1

    float s0 = v.x * w01.x + v.y * w01.z + v.z * w23.x + v.w * w23.z;
    float s1 = v.x * w01.y + v.y * w01.w + v.z * w23.y + v.w * w23.w;
    #pragma unroll
    for (int o = 16; o; o >>= 1) {
        s0 += __shfl_xor_sync(0xFFFFFFFFu, s0, o);
        s1 += __shfl_xor_sync(0xFFFFFFFFu, s1, o);
    }
    if (lane == 0) {
        g_buf0[2 * warp + 0] = s0;
        g_buf0[2 * warp + 1] = s1;
    }
}

// ---------------------------------------------------------------------------
// edge-parallel SpMM in 2-dim space, EPT edges/thread.
// All streaming loads and all random gathers are issued before any RED so the
// warp has EPT independent L2-hit loads in flight (latency hiding).
__global__ void k_scatter(const int4*   __restrict__ row4,
                          const int4*   __restrict__ col4,
                          const float4* __restrict__ val4,
                          int sIdx, int dIdx) {
    int i = blockIdx.x * blockDim.x + threadIdx.x;   // group of EPT edges
    if (i >= N_EDGES / EPT) return;
    int base = i * (EPT / 4);                         // in int4 units

    int4   c0 = col4[base],     c1 = col4[base + 1];
    int4   r0 = row4[base],     r1 = row4[base + 1];
    float4 v0 = val4[base],     v1 = val4[base + 1];

    const float2* cur = reinterpret_cast<const float2*>(buf_of(sIdx));
    float*        dst = buf_of(dIdx);

    // batch all 8 random gathers -> 8 outstanding L2 loads
    float2 x0 = cur[c0.x];
    float2 x1 = cur[c0.y];
    float2 x2 = cur[c0.z];
    float2 x3 = cur[c0.w];
    float2 x4 = cur[c1.x];
    float2 x5 = cur[c1.y];
    float2 x6 = cur[c1.z];
    float2 x7 = cur[c1.w];

    red_add_v2(dst + 2 * r0.x, v0.x * x0.x, v0.x * x0.y);
    red_add_v2(dst + 2 * r0.y, v0.y * x1.x, v0.y * x1.y);
    red_add_v2(dst + 2 * r0.z, v0.z * x2.x, v0.z * x2.y);
    red_add_v2(dst + 2 * r0.w, v0.w * x3.x, v0.w * x3.y);
    red_add_v2(dst + 2 * r1.x, v1.x * x4.x, v1.x * x4.y);
    red_add_v2(dst + 2 * r1.y, v1.y * x5.x, v1.y * x5.y);
    red_add_v2(dst + 2 * r1.z, v1.z * x6.x, v1.z * x6.y);
    red_add_v2(dst + 2 * r1.w, v1.w * x7.x, v1.w * x7.y);
}

// ---------------------------------------------------------------------------
// out = a0*buf0 + a1*buf1 + a2*buf2 + a3*buf3 + b, a = softmax(alpha).
__global__ void k_final(const float* __restrict__ alpha,
                        const float* __restrict__ b,
                        float* __restrict__ out) {
    int i = blockIdx.x * blockDim.x + threadIdx.x;
    if (i >= (2 * N_NODES) / 4) return;

    float al0 = alpha[0], al1 = alpha[1], al2 = alpha[2], al3 = alpha[3];
    float m = fmaxf(fmaxf(al0, al1), fmaxf(al2, al3));
    float e0 = expf(al0 - m), e1 = expf(al1 - m),
          e2 = expf(al2 - m), e3 = expf(al3 - m);
    float inv = 1.f / (e0 + e1 + e2 + e3);
    float a0 = e0 * inv, a1 = e1 * inv, a2 = e2 * inv, a3 = e3 * inv;

    float4 p0 = reinterpret_cast<const float4*>(g_buf0)[i];
    float4 p1 = reinterpret_cast<const float4*>(g_buf1)[i];
    float4 p2 = reinterpret_cast<const float4*>(g_buf2)[i];
    float4 p3 = reinterpret_cast<const float4*>(g_buf3)[i];
    float b0 = b[0], b1 = b[1];

    float4 o;
    o.x = a0 * p0.x + a1 * p1.x + a2 * p2.x + a3 * p3.x + b0;
    o.y = a0 * p0.y + a1 * p1.y + a2 * p2.y + a3 * p3.y + b1;
    o.z = a0 * p0.z + a1 * p1.z + a2 * p2.z + a3 * p3.z + b0;
    o.w = a0 * p0.w + a1 * p1.w + a2 * p2.w + a3 * p3.w + b1;
    reinterpret_cast<float4*>(out)[i] = o;
}

// ---------------------------------------------------------------------------
extern "C" void kernel_launch(void* const* d_in, const int* in_sizes, int n_in,
                              void* d_out, int out_size) {
    const int*   node_idx = (const int*)  d_in[0];
    const int*   adj_row  = (const int*)  d_in[1];
    const int*   adj_col  = (const int*)  d_in[2];
    const float* adj_val  = (const float*)d_in[3];
    const float* emb      = (const float*)d_in[4];
    const float* alpha    = (const float*)d_in[5];
    const float* W        = (const float*)d_in[6];
    const float* b        = (const float*)d_in[7];
    float*       out      = (float*)d_out;

    {   // one warp per node (+ fused zeroing of buf1..buf3)
        int threads = 256;
        int blocks  = (N_NODES * 32 + threads - 1) / threads;
        k_init<<<blocks, threads>>>(node_idx, emb, W);
    }

    const int edgeBlocks = (N_EDGES / EPT + 255) / 256;
    const int4*   row4 = (const int4*)  adj_row;
    const int4*   col4 = (const int4*)  adj_col;
    const float4* val4 = (const float4*)adj_val;

    k_scatter<<<edgeBlocks, 256>>>(row4, col4, val4, 0, 1);
    k_scatter<<<edgeBlocks, 256>>>(row4, col4, val4, 1, 2);
    k_scatter<<<edgeBlocks, 256>>>(row4, col4, val4, 2, 3);

    const int vecBlocks = ((2 * N_NODES) / 4 + 255) / 256;
    k_final<<<vecBlocks, 256>>>(alpha, b, out);
}

// round 6
// speedup vs baseline: 1.0407x; 1.0407x over previous
#include <cuda_runtime.h>

// LightGCN: out = sum_i a_i * A^i X W + b  ==  sum_i a_i * A^i (X W) + b
// Propagate in 2-dim projected space. R6: R4 structure (5 launches, per-power
// buffers, fused epilogue) + scatter reverted to the occupancy-optimal
// 2-edges/thread shape (R5 showed warp count, not per-thread MLP, hides the
// L2 gather/atomic latency; grid must fill the chip's warp slots).

#define N_NODES 100000
#define N_EDGES 1600000
#define DIM     128
#define NLAYERS 3

// buf[i] holds A^i (XW), 2 floats per node.
__device__ __align__(16) float g_buf0[2 * N_NODES];
__device__ __align__(16) float g_buf1[2 * N_NODES];
__device__ __align__(16) float g_buf2[2 * N_NODES];
__device__ __align__(16) float g_buf3[2 * N_NODES];

__device__ __forceinline__ float* buf_of(int i) {
    return i == 0 ? g_buf0 : i == 1 ? g_buf1 : i == 2 ? g_buf2 : g_buf3;
}

// one 8-byte vector RED instead of two scalar float atomics
__device__ __forceinline__ void red_add_v2(float* p, float a, float b) {
    asm volatile("red.global.add.v2.f32 [%0], {%1, %2};"
                 :: "l"(p), "f"(a), "f"(b) : "memory");
}

// ---------------------------------------------------------------------------
// buf0 = (embedding[node_idx]) @ W ; also zero buf1..buf3.
// One warp per node: lane l loads float4 at feature 4l (512B coalesced/warp).
__global__ void k_init(const int* __restrict__ node_idx,
                       const float* __restrict__ emb,
                       const float* __restrict__ W) {
    int gtid = blockIdx.x * blockDim.x + threadIdx.x;
    int warp = gtid >> 5;
    int lane = threadIdx.x & 31;
    if (warp >= N_NODES) return;

    if (gtid < 2 * N_NODES) {
        g_buf1[gtid] = 0.f;
        g_buf2[gtid] = 0.f;
        g_buf3[gtid] = 0.f;
    }

    int src = node_idx[warp];
    float4 v = reinterpret_cast<const float4*>(emb + (long long)src * DIM)[lane];
    const float4* w4 = reinterpret_cast<const float4*>(W + lane * 8);
    float4 w01 = w4[0];   // k0c0 k0c1 k1c0 k1c1
    float4 w23 = w4[1];   // k2c0 k2c1 k3c0 k3c1

    float s0 = v.x * w01.x + v.y * w01.z + v.z * w23.x + v.w * w23.z;
    float s1 = v.x * w01.y + v.y * w01.w + v.z * w23.y + v.w * w23.w;
    #pragma unroll
    for (int o = 16; o; o >>= 1) {
        s0 += __shfl_xor_sync(0xFFFFFFFFu, s0, o);
        s1 += __shfl_xor_sync(0xFFFFFFFFu, s1, o);
    }
    if (lane == 0) {
        g_buf0[2 * warp + 0] = s0;
        g_buf0[2 * warp + 1] = s1;
    }
}

// ---------------------------------------------------------------------------
// edge-parallel SpMM in 2-dim space: buf[d][r] += val * buf[s][c],
// 2 edges/thread (occupancy-optimal), buffers chosen device-side by index.
__global__ void __launch_bounds__(256)
k_scatter(const int2*   __restrict__ row2,
          const int2*   __restrict__ col2,
          const float2* __restrict__ val2,
          int sIdx, int dIdx) {
    int i = blockIdx.x * blockDim.x + threadIdx.x;
    if (i >= N_EDGES / 2) return;
    int2   r = row2[i];
    int2   c = col2[i];
    float2 v = val2[i];
    const float2* cur = reinterpret_cast<const float2*>(buf_of(sIdx));
    float*        dst = buf_of(dIdx);
    float2 x0 = cur[c.x];
    float2 x1 = cur[c.y];
    red_add_v2(dst + 2 * r.x, v.x * x0.x, v.x * x0.y);
    red_add_v2(dst + 2 * r.y, v.y * x1.x, v.y * x1.y);
}

// ---------------------------------------------------------------------------
// out = a0*buf0 + a1*buf1 + a2*buf2 + a3*buf3 + b, a = softmax(alpha).
__global__ void k_final(const float* __restrict__ alpha,
                        const float* __restrict__ b,
                        float* __restrict__ out) {
    int i = blockIdx.x * blockDim.x + threadIdx.x;
    if (i >= (2 * N_NODES) / 4) return;

    float al0 = alpha[0], al1 = alpha[1], al2 = alpha[2], al3 = alpha[3];
    float m = fmaxf(fmaxf(al0, al1), fmaxf(al2, al3));
    float e0 = expf(al0 - m), e1 = expf(al1 - m),
          e2 = expf(al2 - m), e3 = expf(al3 - m);
    float inv = 1.f / (e0 + e1 + e2 + e3);
    float a0 = e0 * inv, a1 = e1 * inv, a2 = e2 * inv, a3 = e3 * inv;

    float4 p0 = reinterpret_cast<const float4*>(g_buf0)[i];
    float4 p1 = reinterpret_cast<const float4*>(g_buf1)[i];
    float4 p2 = reinterpret_cast<const float4*>(g_buf2)[i];
    float4 p3 = reinterpret_cast<const float4*>(g_buf3)[i];
    float b0 = b[0], b1 = b[1];

    float4 o;
    o.x = a0 * p0.x + a1 * p1.x + a2 * p2.x + a3 * p3.x + b0;
    o.y = a0 * p0.y + a1 * p1.y + a2 * p2.y + a3 * p3.y + b1;
    o.z = a0 * p0.z + a1 * p1.z + a2 * p2.z + a3 * p3.z + b0;
    o.w = a0 * p0.w + a1 * p1.w + a2 * p2.w + a3 * p3.w + b1;
    reinterpret_cast<float4*>(out)[i] = o;
}

// ---------------------------------------------------------------------------
extern "C" void kernel_launch(void* const* d_in, const int* in_sizes, int n_in,
                              void* d_out, int out_size) {
    const int*   node_idx = (const int*)  d_in[0];
    const int*   adj_row  = (const int*)  d_in[1];
    const int*   adj_col  = (const int*)  d_in[2];
    const float* adj_val  = (const float*)d_in[3];
    const float* emb      = (const float*)d_in[4];
    const float* alpha    = (const float*)d_in[5];
    const float* W        = (const float*)d_in[6];
    const float* b        = (const float*)d_in[7];
    float*       out      = (float*)d_out;

    {   // one warp per node (+ fused zeroing of buf1..buf3)
        int threads = 256;
        int blocks  = (N_NODES * 32 + threads - 1) / threads;
        k_init<<<blocks, threads>>>(node_idx, emb, W);
    }

    const int edgeBlocks = (N_EDGES / 2 + 255) / 256;
    const int2*   row2 = (const int2*)  adj_row;
    const int2*   col2 = (const int2*)  adj_col;
    const float2* val2 = (const float2*)adj_val;

    k_scatter<<<edgeBlocks, 256>>>(row2, col2, val2, 0, 1);
    k_scatter<<<edgeBlocks, 256>>>(row2, col2, val2, 1, 2);
    k_scatter<<<edgeBlocks, 256>>>(row2, col2, val2, 2, 3);

    const int vecBlocks = ((2 * N_NODES) / 4 + 255) / 256;
    k_final<<<vecBlocks, 256>>>(alpha, b, out);
}